// round 1
// baseline (speedup 1.0000x reference)
#include <cuda_runtime.h>

#define N_ 64
#define C_ 64
#define T_ 300
#define V_ 25
#define F_ 64
#define TPB 5                 // t's per block; 300 % 5 == 0
#define ALPHA 0.2f
#define NEG_INF_ -9.0e15f

__global__ __launch_bounds__(256) void gat_kernel(
    const float* __restrict__ x,    // (N, C, T, V)
    const int*   __restrict__ adj,  // (V, V)
    const float* __restrict__ W,    // (C, F)
    const float* __restrict__ a,    // (2F, 1)
    float*       __restrict__ out)  // (N, F, T, V)
{
    __shared__ float Ws[C_][F_];        // 16 KB
    __shared__ float xs[C_][V_ + 1];    // 6656 B ; also reused as out staging [25][65]
    __shared__ float hs[V_][F_ + 1];    // 6500 B
    __shared__ float att[V_][V_ + 1];   // 2600 B
    __shared__ float f1s[V_], f2s[V_];
    __shared__ float a1s[F_], a2s[F_];
    __shared__ int   adjs[V_][V_];

    const int tid = threadIdx.x;
    const int tx  = tid & 31;   // lane
    const int ty  = tid >> 5;   // warp id 0..7

    // ---- per-CTA constant loads ----
    for (int i = tid; i < C_ * F_; i += 256) Ws[i >> 6][i & 63] = W[i];
    if (tid < F_) { a1s[tid] = a[tid]; a2s[tid] = a[F_ + tid]; }
    for (int i = tid; i < V_ * V_; i += 256) adjs[i / V_][i % V_] = adj[i];

    const int n  = blockIdx.x / (T_ / TPB);
    const int t0 = (blockIdx.x % (T_ / TPB)) * TPB;

    const float* xn   = x   + (size_t)n * C_ * T_ * V_;
    float*       outn = out + (size_t)n * F_ * T_ * V_;

    for (int tt = 0; tt < TPB; ++tt) {
        const int t = t0 + tt;

        __syncthreads();   // protect staging buffer (xs) reads of previous iter

        // ---- load x slice: xs[c][v] = x[n,c,t,v]  (25 contiguous per row) ----
        for (int c = ty; c < C_; c += 8) {
            if (tx < V_) xs[c][tx] = xn[c * (T_ * V_) + t * V_ + tx];
        }
        __syncthreads();

        // ---- h[v][f] = sum_c xs[c][v] * Ws[c][f] ----
        // thread tile: f in {tx, tx+32}; v in {ty, ty+8, ty+16, ty+24} (guard <25)
        float acc[4][2];
        #pragma unroll
        for (int k = 0; k < 4; ++k) { acc[k][0] = 0.f; acc[k][1] = 0.f; }

        #pragma unroll 8
        for (int c = 0; c < C_; ++c) {
            const float w0 = Ws[c][tx];
            const float w1 = Ws[c][tx + 32];
            #pragma unroll
            for (int k = 0; k < 4; ++k) {
                const int v = ty + 8 * k;
                if (v < V_) {
                    const float xv = xs[c][v];
                    acc[k][0] += xv * w0;
                    acc[k][1] += xv * w1;
                }
            }
        }
        #pragma unroll
        for (int k = 0; k < 4; ++k) {
            const int v = ty + 8 * k;
            if (v < V_) { hs[v][tx] = acc[k][0]; hs[v][tx + 32] = acc[k][1]; }
        }
        __syncthreads();

        // ---- f1[i] = h[i,:]·a1 ; f2[i] = h[i,:]·a2 ----
        if (tid < 2 * V_) {
            const int  i   = (tid < V_) ? tid : tid - V_;
            const float* av = (tid < V_) ? a1s : a2s;
            float s = 0.f;
            #pragma unroll 16
            for (int f = 0; f < F_; ++f) s += hs[i][f] * av[f];
            if (tid < V_) f1s[i] = s; else f2s[i] = s;
        }
        __syncthreads();

        // ---- masked leaky-relu attention + row softmax ----
        if (tid < V_) {
            const int i = tid;
            const float fi = f1s[i];
            float m = NEG_INF_;
            #pragma unroll
            for (int j = 0; j < V_; ++j) {
                float e = fi + f2s[j];
                e = (e > 0.f) ? e : ALPHA * e;          // leaky_relu BEFORE mask
                e = (adjs[i][j] > 0) ? e : NEG_INF_;
                att[i][j] = e;
                m = fmaxf(m, e);
            }
            float s = 0.f;
            #pragma unroll
            for (int j = 0; j < V_; ++j) {
                const float p = __expf(att[i][j] - m);
                att[i][j] = p;
                s += p;
            }
            const float inv = 1.f / s;
            #pragma unroll
            for (int j = 0; j < V_; ++j) att[i][j] *= inv;
        }
        __syncthreads();

        // ---- h'[i][f] = sum_j att[i][j]*h[j][f], then elu; stage transposed ----
        float po[4][2];
        #pragma unroll
        for (int k = 0; k < 4; ++k) { po[k][0] = 0.f; po[k][1] = 0.f; }

        #pragma unroll
        for (int j = 0; j < V_; ++j) {
            const float h0 = hs[j][tx];
            const float h1 = hs[j][tx + 32];
            #pragma unroll
            for (int k = 0; k < 4; ++k) {
                const int v = ty + 8 * k;
                if (v < V_) {
                    const float aij = att[v][j];
                    po[k][0] += aij * h0;
                    po[k][1] += aij * h1;
                }
            }
        }

        float* os = &xs[0][0];   // reuse xs as [25][65] staging (stride 65, same as hs pad? no: 26*64=1664 floats >= 25*65=1625)
        #pragma unroll
        for (int k = 0; k < 4; ++k) {
            const int v = ty + 8 * k;
            if (v < V_) {
                float e0 = po[k][0];
                float e1 = po[k][1];
                e0 = (e0 > 0.f) ? e0 : expm1f(e0);
                e1 = (e1 > 0.f) ? e1 : expm1f(e1);
                os[v * 65 + tx]      = e0;
                os[v * 65 + tx + 32] = e1;
            }
        }
        __syncthreads();

        // ---- store out[n,f,t,v]: lane = v (contiguous 25), warp loops f ----
        for (int f = ty; f < F_; f += 8) {
            if (tx < V_) outn[f * (T_ * V_) + t * V_ + tx] = os[tx * 65 + f];
        }
    }
}

extern "C" void kernel_launch(void* const* d_in, const int* in_sizes, int n_in,
                              void* d_out, int out_size)
{
    const float* x   = (const float*)d_in[0];
    const int*   adj = (const int*)  d_in[1];
    const float* W   = (const float*)d_in[2];
    const float* a   = (const float*)d_in[3];
    float* out = (float*)d_out;

    dim3 grid(N_ * (T_ / TPB));
    gat_kernel<<<grid, 256>>>(x, adj, W, a, out);
}

// round 2
// speedup vs baseline: 1.2016x; 1.2016x over previous
#include <cuda_runtime.h>

#define N_ 64
#define C_ 64
#define T_ 300
#define V_ 25
#define F_ 64
#define TPB 5
#define M_ 125                 // TPB * V_
#define MP 128                 // padded M
#define HS_STRIDE 68
#define ATT_STRIDE 28
#define OS_STRIDE 67
#define XS_STRIDE 128
#define ALPHA 0.2f
#define NEG_INF_ -9.0e15f

// shared memory layout (float offsets)
#define OFF_WS   0
#define OFF_HS   (OFF_WS + C_ * F_)              // 4096
#define OFF_ATT  (OFF_HS + MP * HS_STRIDE)       // 12800
#define OFF_XS   (OFF_ATT + MP * ATT_STRIDE)     // 16384  (union: xsT / out staging)
#define XS_SIZE  8704
#define OFF_F1   (OFF_XS + XS_SIZE)              // 25088
#define OFF_F2   (OFF_F1 + MP)
#define OFF_A1   (OFF_F2 + MP)
#define OFF_A2   (OFF_A1 + F_)
#define OFF_ADJ  (OFF_A2 + F_)
#define SMEM_FLOATS (OFF_ADJ + V_ * V_)
#define SMEM_BYTES  (SMEM_FLOATS * 4)            // ~104.4 KB

__global__ void __launch_bounds__(256, 2) gat_kernel(
    const float* __restrict__ x,    // (N, C, T, V)
    const int*   __restrict__ adj,  // (V, V)
    const float* __restrict__ W,    // (C, F)
    const float* __restrict__ a,    // (2F, 1)
    float*       __restrict__ out)  // (N, F, T, V)
{
    extern __shared__ float sm[];
    float* Ws   = sm + OFF_WS;
    float* hs   = sm + OFF_HS;
    float* attm = sm + OFF_ATT;
    float* xsT  = sm + OFF_XS;
    float* f1s  = sm + OFF_F1;
    float* f2s  = sm + OFF_F2;
    float* a1s  = sm + OFF_A1;
    float* a2s  = sm + OFF_A2;
    int*   adjs = (int*)(sm + OFF_ADJ);

    const int tid = threadIdx.x;
    const int tf  = tid & 15;        // 0..15, f0 = 4*tf
    const int tm  = tid >> 4;        // 0..15, m0 = 8*tm
    const int f0  = tf << 2;
    const int m0  = tm << 3;

    // ---- stage constants ----
    for (int i = tid; i < C_ * F_; i += 256) Ws[i] = W[i];
    if (tid < F_) { a1s[tid] = a[tid]; a2s[tid] = a[F_ + tid]; }
    for (int i = tid; i < V_ * V_; i += 256) adjs[i] = adj[i];
    for (int i = tid; i < MP * ATT_STRIDE; i += 256) attm[i] = 0.f;

    const int n  = blockIdx.x / (T_ / TPB);
    const int bt = blockIdx.x % (T_ / TPB);
    const int t0 = bt * TPB;
    const float* xn   = x   + (size_t)n * C_ * T_ * V_ + (size_t)t0 * V_;
    float*       outn = out + (size_t)n * F_ * T_ * V_ + (size_t)t0 * V_;

    // ---- load x: xsT[c][m], m = tt*25+v contiguous in global; zero-pad m>=125 ----
    for (int i = tid; i < C_ * MP; i += 256) {
        const int c = i >> 7;
        const int m = i & 127;
        xsT[c * XS_STRIDE + m] = (m < M_) ? xn[c * (T_ * V_) + m] : 0.f;
    }
    __syncthreads();

    const float4 a1v = *(const float4*)&a1s[f0];
    const float4 a2v = *(const float4*)&a2s[f0];

    // ---- GEMM1: hs[m][f] = sum_c xsT[c][m] * Ws[c][f]; tile 8m x 4f ----
    float acc[8][4];
    #pragma unroll
    for (int k = 0; k < 8; ++k)
        #pragma unroll
        for (int ff = 0; ff < 4; ++ff) acc[k][ff] = 0.f;

    #pragma unroll 8
    for (int c = 0; c < C_; ++c) {
        const float4 wv  = *(const float4*)&Ws[c * F_ + f0];
        const float4 xv0 = *(const float4*)&xsT[c * XS_STRIDE + m0];
        const float4 xv1 = *(const float4*)&xsT[c * XS_STRIDE + m0 + 4];
        const float xm[8] = {xv0.x, xv0.y, xv0.z, xv0.w, xv1.x, xv1.y, xv1.z, xv1.w};
        #pragma unroll
        for (int k = 0; k < 8; ++k) {
            acc[k][0] += xm[k] * wv.x;
            acc[k][1] += xm[k] * wv.y;
            acc[k][2] += xm[k] * wv.z;
            acc[k][3] += xm[k] * wv.w;
        }
    }

    // write hs + partial f1/f2 from accumulators
    float s1[8], s2[8];
    #pragma unroll
    for (int k = 0; k < 8; ++k) {
        *(float4*)&hs[(m0 + k) * HS_STRIDE + f0] =
            make_float4(acc[k][0], acc[k][1], acc[k][2], acc[k][3]);
        s1[k] = acc[k][0] * a1v.x + acc[k][1] * a1v.y + acc[k][2] * a1v.z + acc[k][3] * a1v.w;
        s2[k] = acc[k][0] * a2v.x + acc[k][1] * a2v.y + acc[k][2] * a2v.z + acc[k][3] * a2v.w;
    }
    // reduce across the 16 tf-lanes (xor masks stay within the warp half)
    #pragma unroll
    for (int d = 1; d < 16; d <<= 1) {
        #pragma unroll
        for (int k = 0; k < 8; ++k) {
            s1[k] += __shfl_xor_sync(0xffffffffu, s1[k], d);
            s2[k] += __shfl_xor_sync(0xffffffffu, s2[k], d);
        }
    }
    if (tf == 0) {
        #pragma unroll
        for (int k = 0; k < 8; ++k) { f1s[m0 + k] = s1[k]; f2s[m0 + k] = s2[k]; }
    }
    __syncthreads();

    // ---- masked leaky-relu + row softmax (one thread per row m) ----
    if (tid < M_) {
        const int m  = tid;
        const int tt = m / V_;
        const int i  = m - tt * V_;
        const int jb = tt * V_;
        const float fi = f1s[m];
        float e[V_];
        float mx = NEG_INF_;
        #pragma unroll
        for (int j = 0; j < V_; ++j) {
            float v = fi + f2s[jb + j];
            v = (v > 0.f) ? v : ALPHA * v;
            v = (adjs[i * V_ + j] > 0) ? v : NEG_INF_;
            e[j] = v;
            mx = fmaxf(mx, v);
        }
        float s = 0.f;
        #pragma unroll
        for (int j = 0; j < V_; ++j) { const float p = __expf(e[j] - mx); e[j] = p; s += p; }
        const float inv = 1.f / s;
        #pragma unroll
        for (int j = 0; j < V_; ++j) attm[m * ATT_STRIDE + j] = e[j] * inv;
    }
    __syncthreads();

    // ---- GEMM2: o[m][f] = sum_j attm[m][j] * hs[tt(m)*25 + j][f] ----
    float o[8][4];
    #pragma unroll
    for (int k = 0; k < 8; ++k)
        #pragma unroll
        for (int ff = 0; ff < 4; ++ff) o[k][ff] = 0.f;

    const int baseA = (m0 / V_) * V_;
    int baseB = ((m0 + 7) / V_) * V_;
    if (baseB > 100) baseB = 100;   // clamp (rows >=125 have att==0 anyway)
    const int splitK = baseA + V_;  // k's with m0+k >= splitK use group B

    for (int jb = 0; jb < ATT_STRIDE; jb += 4) {
        float4 hA[4], hB[4];
        #pragma unroll
        for (int jj = 0; jj < 4; ++jj) {
            hA[jj] = *(const float4*)&hs[(baseA + jb + jj) * HS_STRIDE + f0];
            hB[jj] = *(const float4*)&hs[(baseB + jb + jj) * HS_STRIDE + f0];
        }
        #pragma unroll
        for (int k = 0; k < 8; ++k) {
            const float4 av = *(const float4*)&attm[(m0 + k) * ATT_STRIDE + jb];
            const float4* h = (m0 + k >= splitK) ? hB : hA;
            o[k][0] += av.x * h[0].x + av.y * h[1].x + av.z * h[2].x + av.w * h[3].x;
            o[k][1] += av.x * h[0].y + av.y * h[1].y + av.z * h[2].y + av.w * h[3].y;
            o[k][2] += av.x * h[0].z + av.y * h[1].z + av.z * h[2].z + av.w * h[3].z;
            o[k][3] += av.x * h[0].w + av.y * h[1].w + av.z * h[2].w + av.w * h[3].w;
        }
    }

    // ---- ELU + stage transposed (stride 67 -> conflict-free readout) ----
    float* os = xsT;   // reuse; xsT no longer needed
    __syncthreads();   // make sure nobody still reads xsT (paranoia; also orders os writes)
    #pragma unroll
    for (int k = 0; k < 8; ++k)
        #pragma unroll
        for (int ff = 0; ff < 4; ++ff) {
            float v = o[k][ff];
            v = (v > 0.f) ? v : expm1f(v);
            os[(m0 + k) * OS_STRIDE + f0 + ff] = v;
        }
    __syncthreads();

    // ---- store: out[n][f][t0*25 + m], 125 contiguous floats per f ----
    for (int idx = tid; idx < F_ * M_; idx += 256) {
        const int f = idx / M_;
        const int m = idx - f * M_;
        outn[f * (T_ * V_) + m] = os[m * OS_STRIDE + f];
    }
}

extern "C" void kernel_launch(void* const* d_in, const int* in_sizes, int n_in,
                              void* d_out, int out_size)
{
    const float* x   = (const float*)d_in[0];
    const int*   adj = (const int*)  d_in[1];
    const float* W   = (const float*)d_in[2];
    const float* a   = (const float*)d_in[3];
    float* out = (float*)d_out;

    cudaFuncSetAttribute(gat_kernel, cudaFuncAttributeMaxDynamicSharedMemorySize, SMEM_BYTES);
    dim3 grid(N_ * (T_ / TPB));
    gat_kernel<<<grid, 256, SMEM_BYTES>>>(x, adj, W, a, out);
}